// round 4
// baseline (speedup 1.0000x reference)
#include <cuda_runtime.h>

// Problem constants (B,H,W,C fixed by the dataset)
constexpr int B    = 2;
constexpr int Hdim = 128;
constexpr int Wdim = 128;
constexpr int C    = 64;     // channels == BIN == 64
constexpr int KS   = 5;      // 5x5 patch
constexpr int PAD  = KS / 2; // 2

// Tiling
constexpr int TX = 32;           // pixels per CTA in x (one warp-row)
constexpr int TY = 4;            // pixels per CTA in y
constexpr int HX = TX + 2 * PAD; // 36 (halo)
constexpr int HY = TY + 2 * PAD; // 8
constexpr int NV = HX * HY;      // 288 vectors per tensor

// Pad pixel-vector stride to 68 floats: lane stride = 68 floats -> bank (4*l)%32,
// conflict-free within each 8-lane LDS.128 phase.
constexpr int VSTRIDE = C + 4;   // 68
constexpr int SMEM_FLOATS = 2 * NV * VSTRIDE;
constexpr int SMEM_BYTES  = SMEM_FLOATS * 4;   // 156,672 B

__global__ __launch_bounds__(TX * TY)
void refloc_kernel(const float* __restrict__ main_t,
                   const float* __restrict__ ref_t,
                   const float* __restrict__ val_t,
                   float* __restrict__ out)
{
    extern __shared__ float s[];
    float* s_ref = s;
    float* s_val = s + NV * VSTRIDE;

    const int tx  = threadIdx.x;           // 0..31
    const int ty  = threadIdx.y;           // 0..3
    const int tid = ty * TX + tx;          // 0..127
    const int x0  = blockIdx.x * TX;
    const int y0  = blockIdx.y * TY;
    const int b   = blockIdx.z;

    // ---- Stage ref + ref_value tile (with halo, zero padded) into smem ----
    // idx enumerates (vector, float4-chunk); consecutive tids -> contiguous gmem.
    for (int idx = tid; idx < NV * 16; idx += TX * TY) {
        const int c4  = idx & 15;
        const int v   = idx >> 4;
        const int col = v % HX;
        const int row = v / HX;
        const int gx  = x0 + col - PAD;
        const int gy  = y0 + row - PAD;
        float4 rv = make_float4(0.f, 0.f, 0.f, 0.f);
        float4 vv = rv;
        if ((unsigned)gx < (unsigned)Wdim && (unsigned)gy < (unsigned)Hdim) {
            const long base = ((((long)b * Hdim + gy) * Wdim + gx) * C) + c4 * 4;
            rv = *reinterpret_cast<const float4*>(ref_t + base);
            vv = *reinterpret_cast<const float4*>(val_t + base);
        }
        *reinterpret_cast<float4*>(s_ref + v * VSTRIDE + c4 * 4) = rv;
        *reinterpret_cast<float4*>(s_val + v * VSTRIDE + c4 * 4) = vv;
    }
    __syncthreads();

    const int x = x0 + tx;
    const int y = y0 + ty;

    // ---- Load main (query) vector into registers ----
    float4 m[16];
    const float4* mp = reinterpret_cast<const float4*>(
        main_t + (((long)b * Hdim + y) * Wdim + x) * C);
#pragma unroll
    for (int c = 0; c < 16; c++) m[c] = mp[c];

    // ---- Scores: 25 dot-products over C=64 from smem ----
    float sc[KS * KS];
#pragma unroll
    for (int i = 0; i < KS; i++) {
#pragma unroll
        for (int j = 0; j < KS; j++) {
            const float* rp = s_ref + ((ty + i) * HX + (tx + j)) * VSTRIDE;
            float a = 0.f;
#pragma unroll
            for (int c = 0; c < 16; c++) {
                const float4 r = *reinterpret_cast<const float4*>(rp + c * 4);
                a = fmaf(r.x, m[c].x, a);
                a = fmaf(r.y, m[c].y, a);
                a = fmaf(r.z, m[c].z, a);
                a = fmaf(r.w, m[c].w, a);
            }
            sc[i * KS + j] = a;
        }
    }

    // ---- Softmax over 25 (entirely in registers) ----
    float mx = sc[0];
#pragma unroll
    for (int p = 1; p < KS * KS; p++) mx = fmaxf(mx, sc[p]);
    float sum = 0.f;
#pragma unroll
    for (int p = 0; p < KS * KS; p++) { sc[p] = __expf(sc[p] - mx); sum += sc[p]; }
    const float inv = 1.0f / sum;

    // ---- Weighted sum of value patches ----
    float4 o[16];
#pragma unroll
    for (int c = 0; c < 16; c++) o[c] = make_float4(0.f, 0.f, 0.f, 0.f);
#pragma unroll
    for (int i = 0; i < KS; i++) {
#pragma unroll
        for (int j = 0; j < KS; j++) {
            const float w = sc[i * KS + j] * inv;
            const float* vp = s_val + ((ty + i) * HX + (tx + j)) * VSTRIDE;
#pragma unroll
            for (int c = 0; c < 16; c++) {
                const float4 v = *reinterpret_cast<const float4*>(vp + c * 4);
                o[c].x = fmaf(w, v.x, o[c].x);
                o[c].y = fmaf(w, v.y, o[c].y);
                o[c].z = fmaf(w, v.z, o[c].z);
                o[c].w = fmaf(w, v.w, o[c].w);
            }
        }
    }

    // ---- Store output ----
    float4* op = reinterpret_cast<float4*>(
        out + (((long)b * Hdim + y) * Wdim + x) * C);
#pragma unroll
    for (int c = 0; c < 16; c++) op[c] = o[c];
}

extern "C" void kernel_launch(void* const* d_in, const int* in_sizes, int n_in,
                              void* d_out, int out_size)
{
    const float* main_t = (const float*)d_in[0];
    const float* ref_t  = (const float*)d_in[1];
    const float* val_t  = (const float*)d_in[2];
    float* out = (float*)d_out;

    // >48KB dynamic smem opt-in (host attribute set; not a stream op, capture-safe)
    cudaFuncSetAttribute(refloc_kernel,
                         cudaFuncAttributeMaxDynamicSharedMemorySize, SMEM_BYTES);

    dim3 grid(Wdim / TX, Hdim / TY, B);
    dim3 block(TX, TY);
    refloc_kernel<<<grid, block, SMEM_BYTES>>>(main_t, ref_t, val_t, out);
}

// round 5
// speedup vs baseline: 1.3257x; 1.3257x over previous
#include <cuda_runtime.h>
#include <cuda_fp16.h>

// Problem constants
constexpr int B    = 2;
constexpr int Hdim = 128;
constexpr int Wdim = 128;
constexpr int C    = 64;     // channels == BIN == 64
constexpr int KS   = 5;
constexpr int PAD  = KS / 2; // 2

// Tiling: 16x16 pixel tile, 256 threads, halo ratio 400/256 = 1.56
constexpr int TXN = 16;
constexpr int TYN = 16;
constexpr int HX  = TXN + 2 * PAD; // 20
constexpr int HY  = TYN + 2 * PAD; // 20
constexpr int NV  = HX * HY;       // 400 vectors

// ref (fp32): stride 68 floats -> lane bank (4*l)%32, conflict-free per 8-lane phase
constexpr int VSTRIDE_R = C + 4;   // 68 floats
// val (fp16): stride 72 halves (=36 words) -> bank (4*l)%32, conflict-free
constexpr int VSTRIDE_V = C + 8;   // 72 halves

constexpr int SMEM_REF_BYTES = NV * VSTRIDE_R * 4;  // 108,800
constexpr int SMEM_VAL_BYTES = NV * VSTRIDE_V * 2;  //  57,600
constexpr int SMEM_BYTES     = SMEM_REF_BYTES + SMEM_VAL_BYTES; // 166,400

__global__ __launch_bounds__(TXN * TYN)
void refloc_kernel(const float* __restrict__ main_t,
                   const float* __restrict__ ref_t,
                   const float* __restrict__ val_t,
                   float* __restrict__ out)
{
    extern __shared__ float s[];
    float*   s_ref = s;
    __half*  s_val = reinterpret_cast<__half*>(s + NV * VSTRIDE_R);

    const int tx  = threadIdx.x;             // 0..15
    const int ty  = threadIdx.y;             // 0..15
    const int tid = ty * TXN + tx;           // 0..255
    const int x0  = blockIdx.x * TXN;
    const int y0  = blockIdx.y * TYN;
    const int b   = blockIdx.z;

    // ---- Stage ref tile (fp32, halo, zero padded) ----
    for (int idx = tid; idx < NV * 16; idx += TXN * TYN) {
        const int c4  = idx & 15;
        const int v   = idx >> 4;
        const int col = v % HX;
        const int row = v / HX;
        const int gx  = x0 + col - PAD;
        const int gy  = y0 + row - PAD;
        float4 rv = make_float4(0.f, 0.f, 0.f, 0.f);
        if ((unsigned)gx < (unsigned)Wdim && (unsigned)gy < (unsigned)Hdim) {
            const long base = ((((long)b * Hdim + gy) * Wdim + gx) * C) + c4 * 4;
            rv = *reinterpret_cast<const float4*>(ref_t + base);
        }
        *reinterpret_cast<float4*>(s_ref + v * VSTRIDE_R + c4 * 4) = rv;
    }

    // ---- Stage value tile (fp16, halo, zero padded): 8 floats -> 4 half2 per step ----
    for (int idx = tid; idx < NV * 8; idx += TXN * TYN) {
        const int c8  = idx & 7;             // 8-float chunk
        const int v   = idx >> 3;
        const int col = v % HX;
        const int row = v / HX;
        const int gx  = x0 + col - PAD;
        const int gy  = y0 + row - PAD;
        uint4 pk = make_uint4(0u, 0u, 0u, 0u);
        if ((unsigned)gx < (unsigned)Wdim && (unsigned)gy < (unsigned)Hdim) {
            const long base = ((((long)b * Hdim + gy) * Wdim + gx) * C) + c8 * 8;
            const float4 a = *reinterpret_cast<const float4*>(val_t + base);
            const float4 c = *reinterpret_cast<const float4*>(val_t + base + 4);
            __half2 h0 = __floats2half2_rn(a.x, a.y);
            __half2 h1 = __floats2half2_rn(a.z, a.w);
            __half2 h2 = __floats2half2_rn(c.x, c.y);
            __half2 h3 = __floats2half2_rn(c.z, c.w);
            pk.x = *reinterpret_cast<unsigned*>(&h0);
            pk.y = *reinterpret_cast<unsigned*>(&h1);
            pk.z = *reinterpret_cast<unsigned*>(&h2);
            pk.w = *reinterpret_cast<unsigned*>(&h3);
        }
        *reinterpret_cast<uint4*>(s_val + v * VSTRIDE_V + c8 * 8) = pk;
    }
    __syncthreads();

    const int x = x0 + tx;
    const int y = y0 + ty;

    // ---- Load main (query) vector ----
    float4 m[16];
    const float4* mp = reinterpret_cast<const float4*>(
        main_t + (((long)b * Hdim + y) * Wdim + x) * C);
#pragma unroll
    for (int c = 0; c < 16; c++) m[c] = mp[c];

    // ---- Scores: 25 dot-products over C=64, 4-way split accumulators ----
    float sc[KS * KS];
#pragma unroll
    for (int i = 0; i < KS; i++) {
#pragma unroll
        for (int j = 0; j < KS; j++) {
            const float* rp = s_ref + ((ty + i) * HX + (tx + j)) * VSTRIDE_R;
            float a0 = 0.f, a1 = 0.f, a2 = 0.f, a3 = 0.f;
#pragma unroll
            for (int c = 0; c < 16; c++) {
                const float4 r = *reinterpret_cast<const float4*>(rp + c * 4);
                a0 = fmaf(r.x, m[c].x, a0);
                a1 = fmaf(r.y, m[c].y, a1);
                a2 = fmaf(r.z, m[c].z, a2);
                a3 = fmaf(r.w, m[c].w, a3);
            }
            sc[i * KS + j] = (a0 + a1) + (a2 + a3);
        }
    }

    // ---- Softmax over 25 (registers only) ----
    float mx = sc[0];
#pragma unroll
    for (int p = 1; p < KS * KS; p++) mx = fmaxf(mx, sc[p]);
    float sum = 0.f;
#pragma unroll
    for (int p = 0; p < KS * KS; p++) { sc[p] = __expf(sc[p] - mx); sum += sc[p]; }
    const float inv = 1.0f / sum;

    // ---- Weighted sum of fp16 value patches (fp32 accumulate) ----
    float2 o[32];
#pragma unroll
    for (int c = 0; c < 32; c++) o[c] = make_float2(0.f, 0.f);
#pragma unroll
    for (int i = 0; i < KS; i++) {
#pragma unroll
        for (int j = 0; j < KS; j++) {
            const float w = sc[i * KS + j] * inv;
            const uint4* vp = reinterpret_cast<const uint4*>(
                s_val + ((ty + i) * HX + (tx + j)) * VSTRIDE_V);
#pragma unroll
            for (int c = 0; c < 8; c++) {
                const uint4 pk = vp[c];
                const float2 f0 = __half22float2(*reinterpret_cast<const __half2*>(&pk.x));
                const float2 f1 = __half22float2(*reinterpret_cast<const __half2*>(&pk.y));
                const float2 f2 = __half22float2(*reinterpret_cast<const __half2*>(&pk.z));
                const float2 f3 = __half22float2(*reinterpret_cast<const __half2*>(&pk.w));
                o[c * 4 + 0].x = fmaf(w, f0.x, o[c * 4 + 0].x);
                o[c * 4 + 0].y = fmaf(w, f0.y, o[c * 4 + 0].y);
                o[c * 4 + 1].x = fmaf(w, f1.x, o[c * 4 + 1].x);
                o[c * 4 + 1].y = fmaf(w, f1.y, o[c * 4 + 1].y);
                o[c * 4 + 2].x = fmaf(w, f2.x, o[c * 4 + 2].x);
                o[c * 4 + 2].y = fmaf(w, f2.y, o[c * 4 + 2].y);
                o[c * 4 + 3].x = fmaf(w, f3.x, o[c * 4 + 3].x);
                o[c * 4 + 3].y = fmaf(w, f3.y, o[c * 4 + 3].y);
            }
        }
    }

    // ---- Store output ----
    float4* op = reinterpret_cast<float4*>(
        out + (((long)b * Hdim + y) * Wdim + x) * C);
#pragma unroll
    for (int c = 0; c < 16; c++) {
        op[c] = make_float4(o[c * 2].x, o[c * 2].y, o[c * 2 + 1].x, o[c * 2 + 1].y);
    }
}

extern "C" void kernel_launch(void* const* d_in, const int* in_sizes, int n_in,
                              void* d_out, int out_size)
{
    const float* main_t = (const float*)d_in[0];
    const float* ref_t  = (const float*)d_in[1];
    const float* val_t  = (const float*)d_in[2];
    float* out = (float*)d_out;

    cudaFuncSetAttribute(refloc_kernel,
                         cudaFuncAttributeMaxDynamicSharedMemorySize, SMEM_BYTES);

    dim3 grid(Wdim / TXN, Hdim / TYN, B);
    dim3 block(TXN, TYN);
    refloc_kernel<<<grid, block, SMEM_BYTES>>>(main_t, ref_t, val_t, out);
}